// round 14
// baseline (speedup 1.0000x reference)
#include <cuda_runtime.h>
#include <cuda_fp16.h>
#include <cstdint>

// ---------------------------------------------------------------------------
// CrossAttention on GB300 (sm_103a; plain compute_103 -> mma.sync fp16).
// R14: conv becomes a persistent kernel with dynamic tile stealing (kills the
// 2.59-waves-run-as-3 quantization loss). All GEMM math identical to R13
// (single fp16 x single fp16, 2-stage / 2-barrier cp.async pipelines).
// ---------------------------------------------------------------------------

#define NB   4
#define CCH  512
#define HW   1024
#define NHD  8
#define DHEAD 128

typedef __half fp16;

// Scratch (no allocations -> __device__ globals)
__device__ fp16  g_w1[6][9 * 512 * 512];           // [conv][r][co][ci]
__device__ fp16  g_x1[2][NB * HW * CCH];           // [n][hw][ci]
__device__ fp16  g_q1[6][NB * CCH * HW];           // kl,ql,vl,kg,qg,vg
__device__ float g_att[2][NB * NHD * 512 * 512];   // pre-softmax
__device__ fp16  g_a1[2][NB * NHD * 512 * 512];    // post-softmax fp16
__device__ fp16  g_y1[2][NB * CCH * HW];           // y_g, y_l
__device__ fp16  g_wp1[2][512 * 512];
__device__ int   g_ctr;                            // persistent-conv work counter

// ============================ helpers =======================================
__device__ __forceinline__ uint32_t smem_u32(const void* p) {
    uint32_t a;
    asm("{ .reg .u64 t; cvta.to.shared.u64 t, %1; cvt.u32.u64 %0, t; }"
        : "=r"(a) : "l"(p));
    return a;
}

__device__ __forceinline__ void mma_f16(float* c, const uint32_t* a, const uint32_t* b) {
    asm volatile(
        "mma.sync.aligned.m16n8k16.row.col.f32.f16.f16.f32 "
        "{%0,%1,%2,%3}, {%4,%5,%6,%7}, {%8,%9}, {%0,%1,%2,%3};"
        : "+f"(c[0]), "+f"(c[1]), "+f"(c[2]), "+f"(c[3])
        : "r"(a[0]), "r"(a[1]), "r"(a[2]), "r"(a[3]), "r"(b[0]), "r"(b[1]));
}

#define LDSM4(r0, r1, r2, r3, addr) \
    asm volatile("ldmatrix.sync.aligned.m8n8.x4.shared.b16 {%0,%1,%2,%3}, [%4];" \
                 : "=r"(r0), "=r"(r1), "=r"(r2), "=r"(r3) : "r"(addr))

#define LDSM2T(r0, r1, addr) \
    asm volatile("ldmatrix.sync.aligned.m8n8.x2.trans.shared.b16 {%0,%1}, [%2];" \
                 : "=r"(r0), "=r"(r1) : "r"(addr))

#define CPA(dst, src, sz) \
    asm volatile("cp.async.ca.shared.global [%0], [%1], 16, %2;" \
                 :: "r"(dst), "l"(src), "r"(sz) : "memory")
#define CP_COMMIT() asm volatile("cp.async.commit_group;" ::: "memory")
#define CP_WAIT1()  asm volatile("cp.async.wait_group 1;" ::: "memory")
#define CP_WAIT0()  asm volatile("cp.async.wait_group 0;" ::: "memory")

// ============================ prep kernels ==================================
__global__ void reset_ctr() { g_ctr = 0; }

// w [co][ci][3][3] -> [conv][r][co][ci] fp16
__global__ void prep_w3(const float* __restrict__ w0, const float* __restrict__ w1,
                        const float* __restrict__ w2, const float* __restrict__ w3,
                        const float* __restrict__ w4, const float* __restrict__ w5,
                        fp16* __restrict__ wo) {
    const float* ws[6] = {w0, w1, w2, w3, w4, w5};
    int conv = blockIdx.y;
    const float* w = ws[conv];
    int t = blockIdx.x * 256 + threadIdx.x;
    int co = t >> 9, ci = t & 511;
    float v[9];
#pragma unroll
    for (int r = 0; r < 9; ++r) v[r] = w[(size_t)t * 9 + r];
#pragma unroll
    for (int r = 0; r < 9; ++r)
        wo[(((size_t)conv * 9 + r) * 512 + co) * 512 + ci] = __float2half_rn(v[r]);
}
__global__ void prep_wp(const float* __restrict__ wp1, const float* __restrict__ wp2,
                        fp16* __restrict__ wo) {
    int pidx = blockIdx.y;
    const float* w = pidx ? wp2 : wp1;
    int idx = blockIdx.x * 256 + threadIdx.x;
    wo[(size_t)pidx * 512 * 512 + idx] = __float2half_rn(w[idx]);
}
// x [n][c][hw] -> xt [n][hw][c] fp16
__global__ void transpose_x(const float* __restrict__ xl, const float* __restrict__ xg,
                            fp16* __restrict__ xt1) {
    __shared__ float tile[32][33];
    int zt = blockIdx.z, tsel = zt >> 2, n = zt & 3;
    const float* x = (tsel ? xg : xl) + (size_t)n * (CCH * HW);
    size_t ob = (size_t)tsel * NB * HW * CCH + (size_t)n * (HW * CCH);
    int hw0 = blockIdx.x * 32, c0 = blockIdx.y * 32;
    int tx = threadIdx.x, ty = threadIdx.y;
#pragma unroll
    for (int i = 0; i < 32; i += 8)
        tile[ty + i][tx] = x[(size_t)(c0 + ty + i) * HW + hw0 + tx];
    __syncthreads();
#pragma unroll
    for (int i = 0; i < 32; i += 8)
        xt1[ob + (size_t)(hw0 + ty + i) * CCH + c0 + tx] =
            __float2half_rn(tile[tx][ty + i]);
}

// ============================ layout consts =================================
#define ROWB 80
#define MATB (128 * ROWB)             // 10240
#define ROW2 272
#define MATB2 (32 * ROW2)             // 8704
#define STG2 (2 * MATB)               // nn stage: A B          20480
#define SM22 (2 * STG2)               // 2-stage                40960
#define STGN (MATB + MATB2)           // nt stage: A B          18944
#define SMN  (2 * STGN)               // 37888

#define NTILES 768                    // 8 s-tiles * 4 co-tiles * 24 conv*n
#define PCTAS  304                    // persistent CTAs (2 per SM, 152 SMs)

// ======================= mma inner phases (single A) ========================
__device__ __forceinline__ void mma_phase_nn(uint32_t st, uint32_t a_base,
                                             uint32_t b_base, float acc[4][4][4]) {
    uint32_t sA = st, sB = st + MATB;
#pragma unroll
    for (int kt = 0; kt < 2; ++kt) {
        uint32_t aa[4][4], bb[4][2];
#pragma unroll
        for (int mt = 0; mt < 4; ++mt) {
            uint32_t ad = a_base + (uint32_t)(mt * 16 * ROWB + kt * 32);
            LDSM4(aa[mt][0], aa[mt][1], aa[mt][2], aa[mt][3], sA + ad);
        }
#pragma unroll
        for (int p = 0; p < 2; ++p) {
            uint32_t bd = b_base + (uint32_t)(p * 16 * ROWB + kt * 32);
            uint32_t r0, r1, r2, r3;
            LDSM4(r0, r1, r2, r3, sB + bd);
            bb[2 * p][0] = r0; bb[2 * p][1] = r2;
            bb[2 * p + 1][0] = r1; bb[2 * p + 1][1] = r3;
        }
#pragma unroll
        for (int mt = 0; mt < 4; ++mt)
#pragma unroll
            for (int nt = 0; nt < 4; ++nt)
                mma_f16(acc[mt][nt], aa[mt], bb[nt]);
    }
}

__device__ __forceinline__ void mma_phase_nt(uint32_t st, uint32_t a_base,
                                             uint32_t bt_base, float acc[4][4][4]) {
    uint32_t sA = st, sB = st + MATB;
#pragma unroll
    for (int kt = 0; kt < 2; ++kt) {
        uint32_t aa[4][4], bb[4][2];
#pragma unroll
        for (int mt = 0; mt < 4; ++mt) {
            uint32_t ad = a_base + (uint32_t)(mt * 16 * ROWB + kt * 32);
            LDSM4(aa[mt][0], aa[mt][1], aa[mt][2], aa[mt][3], sA + ad);
        }
#pragma unroll
        for (int nt = 0; nt < 4; ++nt) {
            uint32_t bd = bt_base + (uint32_t)(kt * 16 * ROW2 + nt * 16);
            LDSM2T(bb[nt][0], bb[nt][1], sB + bd);
        }
#pragma unroll
        for (int mt = 0; mt < 4; ++mt)
#pragma unroll
            for (int nt = 0; nt < 4; ++nt)
                mma_f16(acc[mt][nt], aa[mt], bb[nt]);
    }
}

// ===== conv 3x3: persistent, dynamic tile stealing, 2-stage / 2-barrier =====
// grid (PCTAS); tiles t: sp = t&7, co = (t>>3)&3, convn = t>>5 (z high bits
// keep concurrently-stolen tiles on the same x tensor for L2 reuse).
__global__ __launch_bounds__(256, 2)
void conv_mma_kernel(const fp16* __restrict__ xt1, const fp16* __restrict__ w1,
                     fp16* __restrict__ q1) {
    extern __shared__ unsigned char dsm[];
    const uint32_t sb = smem_u32(dsm);
    __shared__ int s_tile;

    int tid = threadIdx.x, wid = tid >> 5, lid = tid & 31;
    int warp_m = wid >> 2, warp_n = wid & 3;
    int grp = lid >> 3, lr = lid & 7;
    uint32_t a_base = (uint32_t)((warp_m * 64 + (grp & 1) * 8 + lr) * ROWB + (grp >> 1) * 16);
    uint32_t b_base = (uint32_t)((warp_n * 32 + (grp & 1) * 8 + lr) * ROWB + (grp >> 1) * 16);
    int row = tid >> 1, half = tid & 1;
    uint32_t dstA = (uint32_t)(row * ROWB + half * 32);

    for (;;) {
        if (tid == 0) s_tile = atomicAdd(&g_ctr, 1);
        __syncthreads();                 // also orders s_tile vs prior-tile reads
        int t = s_tile;
        if (t >= NTILES) break;

        int sp0 = (t & 7) * 128;
        int co0 = ((t >> 3) & 3) * 128;
        int zz = t >> 5;
        int conv = zz >> 2, n = zz & 3;
        const fp16* xb = xt1 + ((size_t)(conv < 3 ? 0 : 1) * NB + n) * (HW * CCH);
        const fp16* wb = w1 + (size_t)conv * (9 * 512 * 512);
        fp16* o1 = q1 + ((size_t)conv * NB + n) * (CCH * HW);

        float acc[4][4][4];
#pragma unroll
        for (int mt = 0; mt < 4; ++mt)
#pragma unroll
            for (int nt = 0; nt < 4; ++nt)
#pragma unroll
                for (int k = 0; k < 4; ++k) acc[mt][nt][k] = 0.f;

        auto prefetch = [&](int ch, int st) {
            uint32_t s0b = sb + st * STG2;
            int r = ch >> 4, ci0 = (ch & 15) << 5;
            int dy = r / 3 - 1, dx = r % 3 - 1;
            size_t wof = ((size_t)r * 512 + co0 + row) * 512 + ci0 + half * 16;
            uint32_t da = s0b + dstA;
            CPA(da,      wb + wof,     16u);
            CPA(da + 16, wb + wof + 8, 16u);
            int s = sp0 + row;
            int yy = (s >> 5) + dy, xx = (s & 31) + dx;
            bool ok = ((unsigned)yy < 32u) && ((unsigned)xx < 32u);
            size_t xof = ok ? ((size_t)(yy * 32 + xx) * 512 + ci0 + half * 16) : 0;
            uint32_t sz = ok ? 16u : 0u;
            uint32_t db = s0b + MATB + dstA;
            CPA(db,      xb + xof,     sz);
            CPA(db + 16, xb + xof + 8, sz);
        };

        // proven 2-stage / 2-barrier pipeline
        prefetch(0, 0); CP_COMMIT();
        for (int ch = 0; ch < 144; ++ch) {
            if (ch + 1 < 144) { prefetch(ch + 1, (ch + 1) & 1); CP_COMMIT(); CP_WAIT1(); }
            else CP_WAIT0();
            __syncthreads();
            mma_phase_nn(sb + (ch & 1) * STG2, a_base, b_base, acc);
            __syncthreads();
        }

#pragma unroll
        for (int mt = 0; mt < 4; ++mt) {
            int m = co0 + warp_m * 64 + mt * 16 + (lid >> 2);
#pragma unroll
            for (int nt = 0; nt < 4; ++nt) {
                int sc = sp0 + warp_n * 32 + nt * 8 + (lid & 3) * 2;
                __half2 p0 = __floats2half2_rn(acc[mt][nt][0], acc[mt][nt][1]);
                __half2 p1 = __floats2half2_rn(acc[mt][nt][2], acc[mt][nt][3]);
                *(uint32_t*)&o1[(size_t)m * HW + sc] = *(uint32_t*)&p0;
                *(uint32_t*)&o1[(size_t)(m + 8) * HW + sc] = *(uint32_t*)&p1;
            }
        }
    }
}

// ================== QK^T: single fp16, 2-stage cp.async =====================
// grid (4 ck, 4 cq, 64): z<32 -> (q_g,k_l)->att0 ; z>=32 -> (q_l,k_g)->att1
__global__ __launch_bounds__(256, 2)
void qk_mma_kernel(const fp16* __restrict__ qk1, float* __restrict__ att) {
    extern __shared__ unsigned char dsm[];
    const uint32_t sb = smem_u32(dsm);
    const size_t QKV_N = (size_t)NB * CCH * HW;
    const size_t ATT_N = (size_t)NB * NHD * 512 * 512;

    int tid = threadIdx.x, wid = tid >> 5, lid = tid & 31;
    int warp_m = wid >> 2, warp_n = wid & 3;
    int z = blockIdx.z, sel = z >> 5, nh = z & 31;
    int n = nh >> 3, h = nh & 7;
    int ck0 = blockIdx.x * 128, cq0 = blockIdx.y * 128;
    size_t base = (size_t)n * (CCH * HW) + h * DHEAD;
    const fp16* qb = qk1 + (sel ? 1 : 4) * QKV_N + base;
    const fp16* kb = qk1 + (sel ? 3 : 0) * QKV_N + base;

    float acc[4][4][4];
#pragma unroll
    for (int mt = 0; mt < 4; ++mt)
#pragma unroll
        for (int nt = 0; nt < 4; ++nt)
#pragma unroll
            for (int kk = 0; kk < 4; ++kk) acc[mt][nt][kk] = 0.f;

    int grp = lid >> 3, lr = lid & 7;
    uint32_t a_base = (uint32_t)((warp_m * 64 + (grp & 1) * 8 + lr) * ROWB + (grp >> 1) * 16);
    uint32_t b_base = (uint32_t)((warp_n * 32 + (grp & 1) * 8 + lr) * ROWB + (grp >> 1) * 16);

    int row = tid >> 1, half = tid & 1;
    uint32_t dstA = (uint32_t)(row * ROWB + half * 32);

    auto prefetch = [&](int ch, int st) {
        uint32_t s0b = sb + st * STG2;
        int ci0 = ch << 5;
        size_t qof = (size_t)(cq0 + row) * HW + ci0 + half * 16;
        size_t kof = (size_t)(ck0 + row) * HW + ci0 + half * 16;
        uint32_t da = s0b + dstA;
        CPA(da,      qb + qof,     16u);
        CPA(da + 16, qb + qof + 8, 16u);
        uint32_t db = s0b + MATB + dstA;
        CPA(db,      kb + kof,     16u);
        CPA(db + 16, kb + kof + 8, 16u);
    };

    prefetch(0, 0); CP_COMMIT();
    for (int ch = 0; ch < 4; ++ch) {
        if (ch + 1 < 4) { prefetch(ch + 1, (ch + 1) & 1); CP_COMMIT(); CP_WAIT1(); }
        else CP_WAIT0();
        __syncthreads();
        mma_phase_nn(sb + (ch & 1) * STG2, a_base, b_base, acc);
        __syncthreads();
    }

    const float SC = 0.08838834764831845f;   // 1/sqrt(128)
    float* ab = att + sel * ATT_N + (size_t)(n * NHD + h) * 512 * 512;
#pragma unroll
    for (int mt = 0; mt < 4; ++mt) {
        int m = cq0 + warp_m * 64 + mt * 16 + (lid >> 2);
#pragma unroll
        for (int nt = 0; nt < 4; ++nt) {
            int sc = ck0 + warp_n * 32 + nt * 8 + (lid & 3) * 2;
            *(float2*)(ab + (size_t)m * 512 + sc) =
                make_float2(acc[mt][nt][0] * SC, acc[mt][nt][1] * SC);
            *(float2*)(ab + (size_t)(m + 8) * 512 + sc) =
                make_float2(acc[mt][nt][2] * SC, acc[mt][nt][3] * SC);
        }
    }
}

// ----------------- softmax: fp32 in -> fp16 out ------------------------------
__global__ void softmax_kernel(const float* __restrict__ att, fp16* __restrict__ a1) {
    int row  = blockIdx.x * 8 + (threadIdx.x >> 5);
    int lane = threadIdx.x & 31;
    const float* p = att + (size_t)row * 512;
    fp16* po = a1 + (size_t)row * 512;
    float v[16];
    float m = -1e30f;
#pragma unroll
    for (int i = 0; i < 16; ++i) { v[i] = p[lane + i * 32]; m = fmaxf(m, v[i]); }
#pragma unroll
    for (int o = 16; o; o >>= 1) m = fmaxf(m, __shfl_xor_sync(0xffffffffu, m, o));
    float s = 0.f;
#pragma unroll
    for (int i = 0; i < 16; ++i) { v[i] = __expf(v[i] - m); s += v[i]; }
#pragma unroll
    for (int o = 16; o; o >>= 1) s += __shfl_xor_sync(0xffffffffu, s, o);
    float inv = 1.f / s;
#pragma unroll
    for (int i = 0; i < 16; ++i)
        po[lane + i * 32] = __float2half_rn(v[i] * inv);
}

// ================== AV: single fp16, 2-stage (B trans) ======================
// grid (4 cq, 64): y<32 -> att0 @ v_l -> y_g ; y>=32 -> att1 @ v_g -> y_l
__global__ __launch_bounds__(256, 2)
void av_mma_kernel(const fp16* __restrict__ a1, const fp16* __restrict__ qk1,
                   fp16* __restrict__ y1) {
    extern __shared__ unsigned char dsm[];
    const uint32_t sb = smem_u32(dsm);
    const size_t QKV_N = (size_t)NB * CCH * HW;
    const size_t ATT_N = (size_t)NB * NHD * 512 * 512;

    int tid = threadIdx.x, wid = tid >> 5, lid = tid & 31;
    int warp_m = wid >> 2, warp_n = wid & 3;
    int z = blockIdx.y, sel = z >> 5, nh = z & 31;
    int n = nh >> 3, h = nh & 7;
    int cq0 = blockIdx.x * 128;
    const fp16* ab = a1 + sel * ATT_N + (size_t)(n * NHD + h) * 512 * 512;
    size_t vbo = (size_t)n * (CCH * HW) + h * DHEAD;
    const fp16* vb = qk1 + (sel ? 5 : 2) * QKV_N + vbo;

    float acc[4][4][4];
#pragma unroll
    for (int mt = 0; mt < 4; ++mt)
#pragma unroll
        for (int nt = 0; nt < 4; ++nt)
#pragma unroll
            for (int kk = 0; kk < 4; ++kk) acc[mt][nt][kk] = 0.f;

    int grp = lid >> 3, lr = lid & 7;
    uint32_t a_base = (uint32_t)((warp_m * 64 + (grp & 1) * 8 + lr) * ROWB + (grp >> 1) * 16);
    int l16 = lid & 15;
    uint32_t bt_base = (uint32_t)(l16 * ROW2 + warp_n * 64);

    int row = tid >> 1, half = tid & 1;
    uint32_t dstA = (uint32_t)(row * ROWB + half * 32);
    int ckr = tid >> 3, seg = tid & 7;
    uint32_t dstB = (uint32_t)(ckr * ROW2 + seg * 32);

    auto prefetch = [&](int ch, int st) {
        uint32_t s0b = sb + st * STGN;
        int ci0 = ch << 5;
        size_t aof = (size_t)(cq0 + row) * 512 + ci0 + half * 16;
        uint32_t da = s0b + dstA;
        CPA(da,      ab + aof,     16u);
        CPA(da + 16, ab + aof + 8, 16u);
        size_t vof = (size_t)(ci0 + ckr) * HW + seg * 16;
        uint32_t db = s0b + MATB + dstB;
        CPA(db,      vb + vof,     16u);
        CPA(db + 16, vb + vof + 8, 16u);
    };

    prefetch(0, 0); CP_COMMIT();
    for (int ch = 0; ch < 16; ++ch) {
        if (ch + 1 < 16) { prefetch(ch + 1, (ch + 1) & 1); CP_COMMIT(); CP_WAIT1(); }
        else CP_WAIT0();
        __syncthreads();
        mma_phase_nt(sb + (ch & 1) * STGN, a_base, bt_base, acc);
        __syncthreads();
    }

    fp16* yb = y1 + (sel ? QKV_N : 0) + vbo;
#pragma unroll
    for (int mt = 0; mt < 4; ++mt) {
        int m = cq0 + warp_m * 64 + mt * 16 + (lid >> 2);
#pragma unroll
        for (int nt = 0; nt < 4; ++nt) {
            int dc = warp_n * 32 + nt * 8 + (lid & 3) * 2;
            __half2 p0 = __floats2half2_rn(acc[mt][nt][0], acc[mt][nt][1]);
            __half2 p1 = __floats2half2_rn(acc[mt][nt][2], acc[mt][nt][3]);
            *(uint32_t*)&yb[(size_t)m * HW + dc] = *(uint32_t*)&p0;
            *(uint32_t*)&yb[(size_t)(m + 8) * HW + dc] = *(uint32_t*)&p1;
        }
    }
}

// ========= 1x1 proj + residual: single fp16, 2-stage (B trans) ==============
// grid (8 s, 4 co, 8): z<4 -> Wp1 @ y_l + x_l -> out_l ; else Wp2 @ y_g + x_g
__global__ __launch_bounds__(256, 2)
void proj_mma_kernel(const fp16* __restrict__ y1, const fp16* __restrict__ wp1,
                     const float* __restrict__ x_l, const float* __restrict__ x_g,
                     const float* __restrict__ rwp, float* __restrict__ out) {
    extern __shared__ unsigned char dsm[];
    const uint32_t sb = smem_u32(dsm);
    const size_t QKV_N = (size_t)NB * CCH * HW;

    int tid = threadIdx.x, wid = tid >> 5, lid = tid & 31;
    int warp_m = wid >> 2, warp_n = wid & 3;
    int z = blockIdx.z, sel = z >> 2, n = z & 3;    // sel 0: out_l, 1: out_g
    int sp0 = blockIdx.x * 128, co0 = blockIdx.y * 128;
    const fp16* yb = y1 + (sel ? 0 : QKV_N) + (size_t)n * (CCH * HW);
    const fp16* wb = wp1 + (size_t)sel * 512 * 512;
    const float* xres = sel ? x_g : x_l;
    float* outb = out + (size_t)sel * QKV_N;

    float acc[4][4][4];
#pragma unroll
    for (int mt = 0; mt < 4; ++mt)
#pragma unroll
        for (int nt = 0; nt < 4; ++nt)
#pragma unroll
            for (int kk = 0; kk < 4; ++kk) acc[mt][nt][kk] = 0.f;

    int grp = lid >> 3, lr = lid & 7;
    uint32_t a_base = (uint32_t)((warp_m * 64 + (grp & 1) * 8 + lr) * ROWB + (grp >> 1) * 16);
    int l16 = lid & 15;
    uint32_t bt_base = (uint32_t)(l16 * ROW2 + warp_n * 64);

    int row = tid >> 1, half = tid & 1;
    uint32_t dstA = (uint32_t)(row * ROWB + half * 32);
    int cir = tid >> 3, seg = tid & 7;
    uint32_t dstB = (uint32_t)(cir * ROW2 + seg * 32);

    auto prefetch = [&](int ch, int st) {
        uint32_t s0b = sb + st * STGN;
        int ci0 = ch << 5;
        size_t wof = (size_t)(co0 + row) * 512 + ci0 + half * 16;
        uint32_t da = s0b + dstA;
        CPA(da,      wb + wof,     16u);
        CPA(da + 16, wb + wof + 8, 16u);
        size_t yof = (size_t)(ci0 + cir) * HW + sp0 + seg * 16;
        uint32_t db = s0b + MATB + dstB;
        CPA(db,      yb + yof,     16u);
        CPA(db + 16, yb + yof + 8, 16u);
    };

    prefetch(0, 0); CP_COMMIT();
    for (int ch = 0; ch < 16; ++ch) {
        if (ch + 1 < 16) { prefetch(ch + 1, (ch + 1) & 1); CP_COMMIT(); CP_WAIT1(); }
        else CP_WAIT0();
        __syncthreads();
        mma_phase_nt(sb + (ch & 1) * STGN, a_base, bt_base, acc);
        __syncthreads();
    }

    float rw = *rwp;
#pragma unroll
    for (int mt = 0; mt < 4; ++mt) {
        int m = co0 + warp_m * 64 + mt * 16 + (lid >> 2);
#pragma unroll
        for (int nt = 0; nt < 4; ++nt) {
            int sc = sp0 + warp_n * 32 + nt * 8 + (lid & 3) * 2;
            size_t b0 = ((size_t)n * CCH + m) * HW + sc;
            size_t b1 = ((size_t)n * CCH + m + 8) * HW + sc;
            float2 x0 = *(const float2*)(xres + b0);
            float2 x1 = *(const float2*)(xres + b1);
            *(float2*)(outb + b0) = make_float2(x0.x + rw * acc[mt][nt][0],
                                                x0.y + rw * acc[mt][nt][1]);
            *(float2*)(outb + b1) = make_float2(x1.x + rw * acc[mt][nt][2],
                                                x1.y + rw * acc[mt][nt][3]);
        }
    }
}

// ------------------------------- launcher -----------------------------------
extern "C" void kernel_launch(void* const* d_in, const int* in_sizes, int n_in,
                              void* d_out, int out_size) {
    (void)in_sizes; (void)n_in; (void)out_size;
    const float* x_l = (const float*)d_in[0];
    const float* x_g = (const float*)d_in[1];
    const float* Wp1 = (const float*)d_in[8];
    const float* Wp2 = (const float*)d_in[9];
    const float* rw  = (const float*)d_in[10];
    float* out = (float*)d_out;

    void* p;
    cudaGetSymbolAddress(&p, g_w1);  fp16* w1  = (fp16*)p;
    cudaGetSymbolAddress(&p, g_x1);  fp16* x1  = (fp16*)p;
    cudaGetSymbolAddress(&p, g_q1);  fp16* q1  = (fp16*)p;
    cudaGetSymbolAddress(&p, g_att); float* attp = (float*)p;
    cudaGetSymbolAddress(&p, g_a1);  fp16* a1  = (fp16*)p;
    cudaGetSymbolAddress(&p, g_y1);  fp16* y1  = (fp16*)p;
    cudaGetSymbolAddress(&p, g_wp1); fp16* wp1 = (fp16*)p;

    cudaFuncSetAttribute(conv_mma_kernel, cudaFuncAttributeMaxDynamicSharedMemorySize, SM22);
    cudaFuncSetAttribute(qk_mma_kernel,   cudaFuncAttributeMaxDynamicSharedMemorySize, SM22);
    cudaFuncSetAttribute(av_mma_kernel,   cudaFuncAttributeMaxDynamicSharedMemorySize, SMN);
    cudaFuncSetAttribute(proj_mma_kernel, cudaFuncAttributeMaxDynamicSharedMemorySize, SMN);

    reset_ctr<<<1, 1>>>();
    prep_w3<<<dim3(1024, 6), 256>>>(
        (const float*)d_in[2], (const float*)d_in[3], (const float*)d_in[4],
        (const float*)d_in[5], (const float*)d_in[6], (const float*)d_in[7], w1);
    prep_wp<<<dim3(1024, 2), 256>>>(Wp1, Wp2, wp1);
    transpose_x<<<dim3(32, 16, 8), dim3(32, 8)>>>(x_l, x_g, x1);

    // buffers: 0 kl, 1 ql, 2 vl, 3 kg, 4 qg, 5 vg
    conv_mma_kernel<<<PCTAS, 256, SM22>>>(x1, w1, q1);

    qk_mma_kernel<<<dim3(4, 4, 64), 256, SM22>>>(q1, attp);

    softmax_kernel<<<4096, 256>>>(attp, a1);

    av_mma_kernel<<<dim3(4, 64), 256, SMN>>>(a1, q1, y1);

    proj_mma_kernel<<<dim3(8, 4, 8), 256, SMN>>>(y1, wp1, x_l, x_g, rw, out);
}

// round 15
// speedup vs baseline: 1.6541x; 1.6541x over previous
#include <cuda_runtime.h>
#include <cuda_fp16.h>
#include <cstdint>

// ---------------------------------------------------------------------------
// CrossAttention on GB300 (sm_103a; plain compute_103 -> mma.sync fp16).
// R15: 3x3 convs via Winograd F(2x2,3x3): 2.25x fewer MACs on the legacy-HMMA
// -issue-bound tensor pipe. Transform-domain GEMMs reuse the proven proj-style
// nt kernel (M=512, N=1024, K=512). Attention chain identical to R13.
// ---------------------------------------------------------------------------

#define NB   4
#define CCH  512
#define HW   1024
#define NHD  8
#define DHEAD 128

typedef __half fp16;

// Scratch (no allocations -> __device__ globals)
__device__ fp16  g_U[6 * 16 * 512 * 512];          // [conv][xi][co][ci]
__device__ fp16  g_V[2 * 16 * 512 * 1024];         // [inp][xi][ci][n*256+t]
__device__ fp16  g_C[(size_t)6 * 16 * 512 * 1024]; // [conv][xi][co][n*256+t]
__device__ fp16  g_q1[6][NB * CCH * HW];           // kl,ql,vl,kg,qg,vg
__device__ float g_att[2][NB * NHD * 512 * 512];   // pre-softmax
__device__ fp16  g_a1[2][NB * NHD * 512 * 512];    // post-softmax fp16
__device__ fp16  g_y1[2][NB * CCH * HW];           // y_g, y_l
__device__ fp16  g_wp1[2][512 * 512];

// ============================ helpers =======================================
__device__ __forceinline__ uint32_t smem_u32(const void* p) {
    uint32_t a;
    asm("{ .reg .u64 t; cvta.to.shared.u64 t, %1; cvt.u32.u64 %0, t; }"
        : "=r"(a) : "l"(p));
    return a;
}

__device__ __forceinline__ void mma_f16(float* c, const uint32_t* a, const uint32_t* b) {
    asm volatile(
        "mma.sync.aligned.m16n8k16.row.col.f32.f16.f16.f32 "
        "{%0,%1,%2,%3}, {%4,%5,%6,%7}, {%8,%9}, {%0,%1,%2,%3};"
        : "+f"(c[0]), "+f"(c[1]), "+f"(c[2]), "+f"(c[3])
        : "r"(a[0]), "r"(a[1]), "r"(a[2]), "r"(a[3]), "r"(b[0]), "r"(b[1]));
}

#define LDSM4(r0, r1, r2, r3, addr) \
    asm volatile("ldmatrix.sync.aligned.m8n8.x4.shared.b16 {%0,%1,%2,%3}, [%4];" \
                 : "=r"(r0), "=r"(r1), "=r"(r2), "=r"(r3) : "r"(addr))

#define LDSM2T(r0, r1, addr) \
    asm volatile("ldmatrix.sync.aligned.m8n8.x2.trans.shared.b16 {%0,%1}, [%2];" \
                 : "=r"(r0), "=r"(r1) : "r"(addr))

#define CPA(dst, src, sz) \
    asm volatile("cp.async.ca.shared.global [%0], [%1], 16, %2;" \
                 :: "r"(dst), "l"(src), "r"(sz) : "memory")
#define CP_COMMIT() asm volatile("cp.async.commit_group;" ::: "memory")
#define CP_WAIT1()  asm volatile("cp.async.wait_group 1;" ::: "memory")
#define CP_WAIT0()  asm volatile("cp.async.wait_group 0;" ::: "memory")

// ============================ layout consts =================================
#define ROWB 80
#define MATB (128 * ROWB)             // 10240
#define ROW2 272
#define MATB2 (32 * ROW2)             // 8704
#define STG2 (2 * MATB)               // nn stage: A B          20480
#define SM22 (2 * STG2)               // 2-stage                40960
#define STGN (MATB + MATB2)           // nt stage: A B          18944
#define SMN  (2 * STGN)               // 37888

// ======================== Winograd transform kernels ========================
// U = G g G^T: w [co][ci][3][3] -> U[conv][xi][co][ci] fp16
__global__ void wino_w(const float* __restrict__ w0, const float* __restrict__ w1,
                       const float* __restrict__ w2, const float* __restrict__ w3,
                       const float* __restrict__ w4, const float* __restrict__ w5,
                       fp16* __restrict__ U) {
    const float* ws[6] = {w0, w1, w2, w3, w4, w5};
    int conv = blockIdx.y;
    const float* w = ws[conv];
    int t = blockIdx.x * 256 + threadIdx.x;   // 262144 (co,ci) pairs
    int co = t >> 9, ci = t & 511;
    float g[3][3];
#pragma unroll
    for (int i = 0; i < 9; ++i) g[i / 3][i % 3] = w[(size_t)t * 9 + i];
    float a[4][3];
#pragma unroll
    for (int c = 0; c < 3; ++c) {
        a[0][c] = g[0][c];
        a[1][c] = 0.5f * (g[0][c] + g[1][c] + g[2][c]);
        a[2][c] = 0.5f * (g[0][c] - g[1][c] + g[2][c]);
        a[3][c] = g[2][c];
    }
    float u[4][4];
#pragma unroll
    for (int r = 0; r < 4; ++r) {
        u[r][0] = a[r][0];
        u[r][1] = 0.5f * (a[r][0] + a[r][1] + a[r][2]);
        u[r][2] = 0.5f * (a[r][0] - a[r][1] + a[r][2]);
        u[r][3] = a[r][2];
    }
#pragma unroll
    for (int xi = 0; xi < 16; ++xi)
        U[(((size_t)conv * 16 + xi) * 512 + co) * 512 + ci] =
            __float2half_rn(u[xi >> 2][xi & 3]);
}

// V = B^T d B: x [n][c][32][32] fp32 -> V[inp][xi][ci][n*256+t] fp16
__global__ void wino_v(const float* __restrict__ xl, const float* __restrict__ xg,
                       fp16* __restrict__ V) {
    int z = blockIdx.y;                       // inp*4 + n
    int inp = z >> 2, n = z & 3;
    const float* x = (inp ? xg : xl) + (size_t)n * (CCH * HW);
    int idx = blockIdx.x * 256 + threadIdx.x; // 512*256 -> grid.x = 512
    int ci = idx >> 8, t = idx & 255;
    int ty = t >> 4, tx = t & 15;
    const float* xc = x + (size_t)ci * HW;
    int r0 = 2 * ty - 1, c0 = 2 * tx - 1;
    float d[4][4];
#pragma unroll
    for (int i = 0; i < 4; ++i)
#pragma unroll
        for (int j = 0; j < 4; ++j) {
            int rr = r0 + i, cc = c0 + j;
            d[i][j] = ((unsigned)rr < 32u && (unsigned)cc < 32u)
                          ? xc[rr * 32 + cc] : 0.f;
        }
    float e[4][4];
#pragma unroll
    for (int j = 0; j < 4; ++j) {
        e[0][j] = d[0][j] - d[2][j];
        e[1][j] = d[1][j] + d[2][j];
        e[2][j] = d[2][j] - d[1][j];
        e[3][j] = d[1][j] - d[3][j];
    }
    float v[4][4];
#pragma unroll
    for (int i = 0; i < 4; ++i) {
        v[i][0] = e[i][0] - e[i][2];
        v[i][1] = e[i][1] + e[i][2];
        v[i][2] = e[i][2] - e[i][1];
        v[i][3] = e[i][1] - e[i][3];
    }
#pragma unroll
    for (int xi = 0; xi < 16; ++xi)
        V[(((size_t)inp * 16 + xi) * 512 + ci) * 1024 + n * 256 + t] =
            __float2half_rn(v[xi >> 2][xi & 3]);
}

// Wp fp32 -> fp16
__global__ void prep_wp(const float* __restrict__ wp1, const float* __restrict__ wp2,
                        fp16* __restrict__ wo) {
    int pidx = blockIdx.y;
    const float* w = pidx ? wp2 : wp1;
    int idx = blockIdx.x * 256 + threadIdx.x;
    wo[(size_t)pidx * 512 * 512 + idx] = __float2half_rn(w[idx]);
}

// ======================= mma inner phases (single A) ========================
__device__ __forceinline__ void mma_phase_nn(uint32_t st, uint32_t a_base,
                                             uint32_t b_base, float acc[4][4][4]) {
    uint32_t sA = st, sB = st + MATB;
#pragma unroll
    for (int kt = 0; kt < 2; ++kt) {
        uint32_t aa[4][4], bb[4][2];
#pragma unroll
        for (int mt = 0; mt < 4; ++mt) {
            uint32_t ad = a_base + (uint32_t)(mt * 16 * ROWB + kt * 32);
            LDSM4(aa[mt][0], aa[mt][1], aa[mt][2], aa[mt][3], sA + ad);
        }
#pragma unroll
        for (int p = 0; p < 2; ++p) {
            uint32_t bd = b_base + (uint32_t)(p * 16 * ROWB + kt * 32);
            uint32_t r0, r1, r2, r3;
            LDSM4(r0, r1, r2, r3, sB + bd);
            bb[2 * p][0] = r0; bb[2 * p][1] = r2;
            bb[2 * p + 1][0] = r1; bb[2 * p + 1][1] = r3;
        }
#pragma unroll
        for (int mt = 0; mt < 4; ++mt)
#pragma unroll
            for (int nt = 0; nt < 4; ++nt)
                mma_f16(acc[mt][nt], aa[mt], bb[nt]);
    }
}

__device__ __forceinline__ void mma_phase_nt(uint32_t st, uint32_t a_base,
                                             uint32_t bt_base, float acc[4][4][4]) {
    uint32_t sA = st, sB = st + MATB;
#pragma unroll
    for (int kt = 0; kt < 2; ++kt) {
        uint32_t aa[4][4], bb[4][2];
#pragma unroll
        for (int mt = 0; mt < 4; ++mt) {
            uint32_t ad = a_base + (uint32_t)(mt * 16 * ROWB + kt * 32);
            LDSM4(aa[mt][0], aa[mt][1], aa[mt][2], aa[mt][3], sA + ad);
        }
#pragma unroll
        for (int nt = 0; nt < 4; ++nt) {
            uint32_t bd = bt_base + (uint32_t)(kt * 16 * ROW2 + nt * 16);
            LDSM2T(bb[nt][0], bb[nt][1], sB + bd);
        }
#pragma unroll
        for (int mt = 0; mt < 4; ++mt)
#pragma unroll
            for (int nt = 0; nt < 4; ++nt)
                mma_f16(acc[mt][nt], aa[mt], bb[nt]);
    }
}

// ============ Winograd-domain GEMM: C[xi] = U[xi] x V[xi] ===================
// grid (8 tile-chunks, 4 co-chunks, 96 = conv*16+xi). Proven proj structure.
__global__ __launch_bounds__(256, 2)
void wino_gemm(const fp16* __restrict__ U, const fp16* __restrict__ V,
               fp16* __restrict__ C) {
    extern __shared__ unsigned char dsm[];
    const uint32_t sb = smem_u32(dsm);

    int tid = threadIdx.x, wid = tid >> 5, lid = tid & 31;
    int warp_m = wid >> 2, warp_n = wid & 3;
    int z = blockIdx.z;
    int conv = z >> 4, xi = z & 15;
    int inp = (conv < 3) ? 0 : 1;
    int tile0 = blockIdx.x * 128, co0 = blockIdx.y * 128;
    const fp16* A = U + ((size_t)conv * 16 + xi) * 512 * 512;
    const fp16* B = V + ((size_t)inp * 16 + xi) * 512 * 1024;
    fp16* Cb = C + ((size_t)conv * 16 + xi) * 512 * 1024;

    float acc[4][4][4];
#pragma unroll
    for (int mt = 0; mt < 4; ++mt)
#pragma unroll
        for (int nt = 0; nt < 4; ++nt)
#pragma unroll
            for (int kk = 0; kk < 4; ++kk) acc[mt][nt][kk] = 0.f;

    int grp = lid >> 3, lr = lid & 7;
    uint32_t a_base = (uint32_t)((warp_m * 64 + (grp & 1) * 8 + lr) * ROWB + (grp >> 1) * 16);
    int l16 = lid & 15;
    uint32_t bt_base = (uint32_t)(l16 * ROW2 + warp_n * 64);

    int row = tid >> 1, half = tid & 1;
    uint32_t dstA = (uint32_t)(row * ROWB + half * 32);
    int cir = tid >> 3, seg = tid & 7;
    uint32_t dstB = (uint32_t)(cir * ROW2 + seg * 32);

    auto prefetch = [&](int ch, int st) {
        uint32_t s0b = sb + st * STGN;
        int ci0 = ch << 5;
        size_t wof = (size_t)(co0 + row) * 512 + ci0 + half * 16;
        uint32_t da = s0b + dstA;
        CPA(da,      A + wof,     16u);
        CPA(da + 16, A + wof + 8, 16u);
        size_t bof = (size_t)(ci0 + cir) * 1024 + tile0 + seg * 16;
        uint32_t db = s0b + MATB + dstB;
        CPA(db,      B + bof,     16u);
        CPA(db + 16, B + bof + 8, 16u);
    };

    prefetch(0, 0); CP_COMMIT();
    for (int ch = 0; ch < 16; ++ch) {
        if (ch + 1 < 16) { prefetch(ch + 1, (ch + 1) & 1); CP_COMMIT(); CP_WAIT1(); }
        else CP_WAIT0();
        __syncthreads();
        mma_phase_nt(sb + (ch & 1) * STGN, a_base, bt_base, acc);
        __syncthreads();
    }

#pragma unroll
    for (int mt = 0; mt < 4; ++mt) {
        int m = co0 + warp_m * 64 + mt * 16 + (lid >> 2);
#pragma unroll
        for (int nt = 0; nt < 4; ++nt) {
            int sc = tile0 + warp_n * 32 + nt * 8 + (lid & 3) * 2;
            __half2 p0 = __floats2half2_rn(acc[mt][nt][0], acc[mt][nt][1]);
            __half2 p1 = __floats2half2_rn(acc[mt][nt][2], acc[mt][nt][3]);
            *(uint32_t*)&Cb[(size_t)m * 1024 + sc] = *(uint32_t*)&p0;
            *(uint32_t*)&Cb[(size_t)(m + 8) * 1024 + sc] = *(uint32_t*)&p1;
        }
    }
}

// ================ inverse transform: Y = A^T M A -> qkv =====================
// grid (512, 4 n, 6 conv); thread = (co, tile)
__global__ void wino_inv(const fp16* __restrict__ C, fp16* __restrict__ q1) {
    int conv = blockIdx.z, n = blockIdx.y;
    int idx = blockIdx.x * 256 + threadIdx.x;   // 512*256
    int co = idx >> 8, t = idx & 255;
    int ty = t >> 4, tx = t & 15;
    const size_t XSTR = (size_t)512 * 1024;
    size_t base = (size_t)conv * 16 * XSTR + (size_t)co * 1024 + n * 256 + t;
    float m[4][4];
#pragma unroll
    for (int xi = 0; xi < 16; ++xi)
        m[xi >> 2][xi & 3] = __half2float(C[base + (size_t)xi * XSTR]);
    float p[2][4];
#pragma unroll
    for (int j = 0; j < 4; ++j) {
        p[0][j] = m[0][j] + m[1][j] + m[2][j];
        p[1][j] = m[1][j] - m[2][j] - m[3][j];
    }
    float y00 = p[0][0] + p[0][1] + p[0][2];
    float y01 = p[0][1] - p[0][2] - p[0][3];
    float y10 = p[1][0] + p[1][1] + p[1][2];
    float y11 = p[1][1] - p[1][2] - p[1][3];
    fp16* o = q1 + ((size_t)conv * NB + n) * (CCH * HW) + (size_t)co * HW;
    int oy = 2 * ty, ox = 2 * tx;
    __half2 r0 = __floats2half2_rn(y00, y01);
    __half2 r1 = __floats2half2_rn(y10, y11);
    *(uint32_t*)&o[oy * 32 + ox] = *(uint32_t*)&r0;
    *(uint32_t*)&o[(oy + 1) * 32 + ox] = *(uint32_t*)&r1;
}

// ================== QK^T: single fp16, 2-stage cp.async =====================
// grid (4 ck, 4 cq, 64): z<32 -> (q_g,k_l)->att0 ; z>=32 -> (q_l,k_g)->att1
__global__ __launch_bounds__(256, 2)
void qk_mma_kernel(const fp16* __restrict__ qk1, float* __restrict__ att) {
    extern __shared__ unsigned char dsm[];
    const uint32_t sb = smem_u32(dsm);
    const size_t QKV_N = (size_t)NB * CCH * HW;
    const size_t ATT_N = (size_t)NB * NHD * 512 * 512;

    int tid = threadIdx.x, wid = tid >> 5, lid = tid & 31;
    int warp_m = wid >> 2, warp_n = wid & 3;
    int z = blockIdx.z, sel = z >> 5, nh = z & 31;
    int n = nh >> 3, h = nh & 7;
    int ck0 = blockIdx.x * 128, cq0 = blockIdx.y * 128;
    size_t base = (size_t)n * (CCH * HW) + h * DHEAD;
    const fp16* qb = qk1 + (sel ? 1 : 4) * QKV_N + base;
    const fp16* kb = qk1 + (sel ? 3 : 0) * QKV_N + base;

    float acc[4][4][4];
#pragma unroll
    for (int mt = 0; mt < 4; ++mt)
#pragma unroll
        for (int nt = 0; nt < 4; ++nt)
#pragma unroll
            for (int kk = 0; kk < 4; ++kk) acc[mt][nt][kk] = 0.f;

    int grp = lid >> 3, lr = lid & 7;
    uint32_t a_base = (uint32_t)((warp_m * 64 + (grp & 1) * 8 + lr) * ROWB + (grp >> 1) * 16);
    uint32_t b_base = (uint32_t)((warp_n * 32 + (grp & 1) * 8 + lr) * ROWB + (grp >> 1) * 16);

    int row = tid >> 1, half = tid & 1;
    uint32_t dstA = (uint32_t)(row * ROWB + half * 32);

    auto prefetch = [&](int ch, int st) {
        uint32_t s0b = sb + st * STG2;
        int ci0 = ch << 5;
        size_t qof = (size_t)(cq0 + row) * HW + ci0 + half * 16;
        size_t kof = (size_t)(ck0 + row) * HW + ci0 + half * 16;
        uint32_t da = s0b + dstA;
        CPA(da,      qb + qof,     16u);
        CPA(da + 16, qb + qof + 8, 16u);
        uint32_t db = s0b + MATB + dstA;
        CPA(db,      kb + kof,     16u);
        CPA(db + 16, kb + kof + 8, 16u);
    };

    prefetch(0, 0); CP_COMMIT();
    for (int ch = 0; ch < 4; ++ch) {
        if (ch + 1 < 4) { prefetch(ch + 1, (ch + 1) & 1); CP_COMMIT(); CP_WAIT1(); }
        else CP_WAIT0();
        __syncthreads();
        mma_phase_nn(sb + (ch & 1) * STG2, a_base, b_base, acc);
        __syncthreads();
    }

    const float SC = 0.08838834764831845f;   // 1/sqrt(128)
    float* ab = att + sel * ATT_N + (size_t)(n * NHD + h) * 512 * 512;
#pragma unroll
    for (int mt = 0; mt < 4; ++mt) {
        int m = cq0 + warp_m * 64 + mt * 16 + (lid >> 2);
#pragma unroll
        for (int nt = 0; nt < 4; ++nt) {
            int sc = ck0 + warp_n * 32 + nt * 8 + (lid & 3) * 2;
            *(float2*)(ab + (size_t)m * 512 + sc) =
                make_float2(acc[mt][nt][0] * SC, acc[mt][nt][1] * SC);
            *(float2*)(ab + (size_t)(m + 8) * 512 + sc) =
                make_float2(acc[mt][nt][2] * SC, acc[mt][nt][3] * SC);
        }
    }
}

// ----------------- softmax: fp32 in -> fp16 out ------------------------------
__global__ void softmax_kernel(const float* __restrict__ att, fp16* __restrict__ a1) {
    int row  = blockIdx.x * 8 + (threadIdx.x >> 5);
    int lane = threadIdx.x & 31;
    const float* p = att + (size_t)row * 512;
    fp16* po = a1 + (size_t)row * 512;
    float v[16];
    float m = -1e30f;
#pragma unroll
    for (int i = 0; i < 16; ++i) { v[i] = p[lane + i * 32]; m = fmaxf(m, v[i]); }
#pragma unroll
    for (int o = 16; o; o >>= 1) m = fmaxf(m, __shfl_xor_sync(0xffffffffu, m, o));
    float s = 0.f;
#pragma unroll
    for (int i = 0; i < 16; ++i) { v[i] = __expf(v[i] - m); s += v[i]; }
#pragma unroll
    for (int o = 16; o; o >>= 1) s += __shfl_xor_sync(0xffffffffu, s, o);
    float inv = 1.f / s;
#pragma unroll
    for (int i = 0; i < 16; ++i)
        po[lane + i * 32] = __float2half_rn(v[i] * inv);
}

// ================== AV: single fp16, 2-stage (B trans) ======================
// grid (4 cq, 64): y<32 -> att0 @ v_l -> y_g ; y>=32 -> att1 @ v_g -> y_l
__global__ __launch_bounds__(256, 2)
void av_mma_kernel(const fp16* __restrict__ a1, const fp16* __restrict__ qk1,
                   fp16* __restrict__ y1) {
    extern __shared__ unsigned char dsm[];
    const uint32_t sb = smem_u32(dsm);
    const size_t QKV_N = (size_t)NB * CCH * HW;
    const size_t ATT_N = (size_t)NB * NHD * 512 * 512;

    int tid = threadIdx.x, wid = tid >> 5, lid = tid & 31;
    int warp_m = wid >> 2, warp_n = wid & 3;
    int z = blockIdx.y, sel = z >> 5, nh = z & 31;
    int n = nh >> 3, h = nh & 7;
    int cq0 = blockIdx.x * 128;
    const fp16* ab = a1 + sel * ATT_N + (size_t)(n * NHD + h) * 512 * 512;
    size_t vbo = (size_t)n * (CCH * HW) + h * DHEAD;
    const fp16* vb = qk1 + (sel ? 5 : 2) * QKV_N + vbo;

    float acc[4][4][4];
#pragma unroll
    for (int mt = 0; mt < 4; ++mt)
#pragma unroll
        for (int nt = 0; nt < 4; ++nt)
#pragma unroll
            for (int kk = 0; kk < 4; ++kk) acc[mt][nt][kk] = 0.f;

    int grp = lid >> 3, lr = lid & 7;
    uint32_t a_base = (uint32_t)((warp_m * 64 + (grp & 1) * 8 + lr) * ROWB + (grp >> 1) * 16);
    int l16 = lid & 15;
    uint32_t bt_base = (uint32_t)(l16 * ROW2 + warp_n * 64);

    int row = tid >> 1, half = tid & 1;
    uint32_t dstA = (uint32_t)(row * ROWB + half * 32);
    int ckr = tid >> 3, seg = tid & 7;
    uint32_t dstB = (uint32_t)(ckr * ROW2 + seg * 32);

    auto prefetch = [&](int ch, int st) {
        uint32_t s0b = sb + st * STGN;
        int ci0 = ch << 5;
        size_t aof = (size_t)(cq0 + row) * 512 + ci0 + half * 16;
        uint32_t da = s0b + dstA;
        CPA(da,      ab + aof,     16u);
        CPA(da + 16, ab + aof + 8, 16u);
        size_t vof = (size_t)(ci0 + ckr) * HW + seg * 16;
        uint32_t db = s0b + MATB + dstB;
        CPA(db,      vb + vof,     16u);
        CPA(db + 16, vb + vof + 8, 16u);
    };

    prefetch(0, 0); CP_COMMIT();
    for (int ch = 0; ch < 16; ++ch) {
        if (ch + 1 < 16) { prefetch(ch + 1, (ch + 1) & 1); CP_COMMIT(); CP_WAIT1(); }
        else CP_WAIT0();
        __syncthreads();
        mma_phase_nt(sb + (ch & 1) * STGN, a_base, bt_base, acc);
        __syncthreads();
    }

    fp16* yb = y1 + (sel ? QKV_N : 0) + vbo;
#pragma unroll
    for (int mt = 0; mt < 4; ++mt) {
        int m = cq0 + warp_m * 64 + mt * 16 + (lid >> 2);
#pragma unroll
        for (int nt = 0; nt < 4; ++nt) {
            int dc = warp_n * 32 + nt * 8 + (lid & 3) * 2;
            __half2 p0 = __floats2half2_rn(acc[mt][nt][0], acc[mt][nt][1]);
            __half2 p1 = __floats2half2_rn(acc[mt][nt][2], acc[mt][nt][3]);
            *(uint32_t*)&yb[(size_t)m * HW + dc] = *(uint32_t*)&p0;
            *(uint32_t*)&yb[(size_t)(m + 8) * HW + dc] = *(uint32_t*)&p1;
        }
    }
}

// ========= 1x1 proj + residual: single fp16, 2-stage (B trans) ==============
// grid (8 s, 4 co, 8): z<4 -> Wp1 @ y_l + x_l -> out_l ; else Wp2 @ y_g + x_g
__global__ __launch_bounds__(256, 2)
void proj_mma_kernel(const fp16* __restrict__ y1, const fp16* __restrict__ wp1,
                     const float* __restrict__ x_l, const float* __restrict__ x_g,
                     const float* __restrict__ rwp, float* __restrict__ out) {
    extern __shared__ unsigned char dsm[];
    const uint32_t sb = smem_u32(dsm);
    const size_t QKV_N = (size_t)NB * CCH * HW;

    int tid = threadIdx.x, wid = tid >> 5, lid = tid & 31;
    int warp_m = wid >> 2, warp_n = wid & 3;
    int z = blockIdx.z, sel = z >> 2, n = z & 3;    // sel 0: out_l, 1: out_g
    int sp0 = blockIdx.x * 128, co0 = blockIdx.y * 128;
    const fp16* yb = y1 + (sel ? 0 : QKV_N) + (size_t)n * (CCH * HW);
    const fp16* wb = wp1 + (size_t)sel * 512 * 512;
    const float* xres = sel ? x_g : x_l;
    float* outb = out + (size_t)sel * QKV_N;

    float acc[4][4][4];
#pragma unroll
    for (int mt = 0; mt < 4; ++mt)
#pragma unroll
        for (int nt = 0; nt < 4; ++nt)
#pragma unroll
            for (int kk = 0; kk < 4; ++kk) acc[mt][nt][kk] = 0.f;

    int grp = lid >> 3, lr = lid & 7;
    uint32_t a_base = (uint32_t)((warp_m * 64 + (grp & 1) * 8 + lr) * ROWB + (grp >> 1) * 16);
    int l16 = lid & 15;
    uint32_t bt_base = (uint32_t)(l16 * ROW2 + warp_n * 64);

    int row = tid >> 1, half = tid & 1;
    uint32_t dstA = (uint32_t)(row * ROWB + half * 32);
    int cir = tid >> 3, seg = tid & 7;
    uint32_t dstB = (uint32_t)(cir * ROW2 + seg * 32);

    auto prefetch = [&](int ch, int st) {
        uint32_t s0b = sb + st * STGN;
        int ci0 = ch << 5;
        size_t wof = (size_t)(co0 + row) * 512 + ci0 + half * 16;
        uint32_t da = s0b + dstA;
        CPA(da,      wb + wof,     16u);
        CPA(da + 16, wb + wof + 8, 16u);
        size_t yof = (size_t)(ci0 + cir) * HW + sp0 + seg * 16;
        uint32_t db = s0b + MATB + dstB;
        CPA(db,      yb + yof,     16u);
        CPA(db + 16, yb + yof + 8, 16u);
    };

    prefetch(0, 0); CP_COMMIT();
    for (int ch = 0; ch < 16; ++ch) {
        if (ch + 1 < 16) { prefetch(ch + 1, (ch + 1) & 1); CP_COMMIT(); CP_WAIT1(); }
        else CP_WAIT0();
        __syncthreads();
        mma_phase_nt(sb + (ch & 1) * STGN, a_base, bt_base, acc);
        __syncthreads();
    }

    float rw = *rwp;
#pragma unroll
    for (int mt = 0; mt < 4; ++mt) {
        int m = co0 + warp_m * 64 + mt * 16 + (lid >> 2);
#pragma unroll
        for (int nt = 0; nt < 4; ++nt) {
            int sc = sp0 + warp_n * 32 + nt * 8 + (lid & 3) * 2;
            size_t b0 = ((size_t)n * CCH + m) * HW + sc;
            size_t b1 = ((size_t)n * CCH + m + 8) * HW + sc;
            float2 x0 = *(const float2*)(xres + b0);
            float2 x1 = *(const float2*)(xres + b1);
            *(float2*)(outb + b0) = make_float2(x0.x + rw * acc[mt][nt][0],
                                                x0.y + rw * acc[mt][nt][1]);
            *(float2*)(outb + b1) = make_float2(x1.x + rw * acc[mt][nt][2],
                                                x1.y + rw * acc[mt][nt][3]);
        }
    }
}

// ------------------------------- launcher -----------------------------------
extern "C" void kernel_launch(void* const* d_in, const int* in_sizes, int n_in,
                              void* d_out, int out_size) {
    (void)in_sizes; (void)n_in; (void)out_size;
    const float* x_l = (const float*)d_in[0];
    const float* x_g = (const float*)d_in[1];
    const float* Wp1 = (const float*)d_in[8];
    const float* Wp2 = (const float*)d_in[9];
    const float* rw  = (const float*)d_in[10];
    float* out = (float*)d_out;

    void* p;
    cudaGetSymbolAddress(&p, g_U);   fp16* U   = (fp16*)p;
    cudaGetSymbolAddress(&p, g_V);   fp16* V   = (fp16*)p;
    cudaGetSymbolAddress(&p, g_C);   fp16* C   = (fp16*)p;
    cudaGetSymbolAddress(&p, g_q1);  fp16* q1  = (fp16*)p;
    cudaGetSymbolAddress(&p, g_att); float* attp = (float*)p;
    cudaGetSymbolAddress(&p, g_a1);  fp16* a1  = (fp16*)p;
    cudaGetSymbolAddress(&p, g_y1);  fp16* y1  = (fp16*)p;
    cudaGetSymbolAddress(&p, g_wp1); fp16* wp1 = (fp16*)p;

    cudaFuncSetAttribute(wino_gemm,       cudaFuncAttributeMaxDynamicSharedMemorySize, SMN);
    cudaFuncSetAttribute(qk_mma_kernel,   cudaFuncAttributeMaxDynamicSharedMemorySize, SM22);
    cudaFuncSetAttribute(av_mma_kernel,   cudaFuncAttributeMaxDynamicSharedMemorySize, SMN);
    cudaFuncSetAttribute(proj_mma_kernel, cudaFuncAttributeMaxDynamicSharedMemorySize, SMN);

    wino_w<<<dim3(1024, 6), 256>>>(
        (const float*)d_in[2], (const float*)d_in[3], (const float*)d_in[4],
        (const float*)d_in[5], (const float*)d_in[6], (const float*)d_in[7], U);
    wino_v<<<dim3(512, 8), 256>>>(x_l, x_g, V);
    prep_wp<<<dim3(1024, 2), 256>>>(Wp1, Wp2, wp1);

    wino_gemm<<<dim3(8, 4, 96), 256, SMN>>>(U, V, C);
    wino_inv<<<dim3(512, 4, 6), 256>>>(C, q1);

    qk_mma_kernel<<<dim3(4, 4, 64), 256, SM22>>>(q1, attp);

    softmax_kernel<<<4096, 256>>>(attp, a1);

    av_mma_kernel<<<dim3(4, 64), 256, SMN>>>(a1, q1, y1);

    proj_mma_kernel<<<dim3(8, 4, 8), 256, SMN>>>(y1, wp1, x_l, x_g, rw, out);
}

// round 16
// speedup vs baseline: 2.2348x; 1.3510x over previous
#include <cuda_runtime.h>
#include <cuda_fp16.h>
#include <cstdint>

// ---------------------------------------------------------------------------
// CrossAttention on GB300 (sm_103a; plain compute_103 -> mma.sync fp16).
// R16: 3x3 convs via Winograd F(4x4,3x3) (36 mults / 16 outputs = 2.25/out,
// 1.78x fewer MMAs than R15's F(2x2,3x3)). Transforms fp32, operands fp16.
// Attention chain identical to R13/R15.
// ---------------------------------------------------------------------------

#define NB   4
#define CCH  512
#define HW   1024
#define NHD  8
#define DHEAD 128

typedef __half fp16;

// Scratch (no allocations -> __device__ globals)
__device__ fp16  g_U[(size_t)6 * 36 * 512 * 512];  // [conv][xi][co][ci]
__device__ fp16  g_V[(size_t)2 * 36 * 512 * 256];  // [inp][xi][ci][n*64+t]
__device__ fp16  g_C[(size_t)6 * 36 * 512 * 256];  // [conv][xi][co][n*64+t]
__device__ fp16  g_q1[6][NB * CCH * HW];           // kl,ql,vl,kg,qg,vg
__device__ float g_att[2][NB * NHD * 512 * 512];   // pre-softmax
__device__ fp16  g_a1[2][NB * NHD * 512 * 512];    // post-softmax fp16
__device__ fp16  g_y1[2][NB * CCH * HW];           // y_g, y_l
__device__ fp16  g_wp1[2][512 * 512];

// ============================ helpers =======================================
__device__ __forceinline__ uint32_t smem_u32(const void* p) {
    uint32_t a;
    asm("{ .reg .u64 t; cvta.to.shared.u64 t, %1; cvt.u32.u64 %0, t; }"
        : "=r"(a) : "l"(p));
    return a;
}

__device__ __forceinline__ void mma_f16(float* c, const uint32_t* a, const uint32_t* b) {
    asm volatile(
        "mma.sync.aligned.m16n8k16.row.col.f32.f16.f16.f32 "
        "{%0,%1,%2,%3}, {%4,%5,%6,%7}, {%8,%9}, {%0,%1,%2,%3};"
        : "+f"(c[0]), "+f"(c[1]), "+f"(c[2]), "+f"(c[3])
        : "r"(a[0]), "r"(a[1]), "r"(a[2]), "r"(a[3]), "r"(b[0]), "r"(b[1]));
}

#define LDSM4(r0, r1, r2, r3, addr) \
    asm volatile("ldmatrix.sync.aligned.m8n8.x4.shared.b16 {%0,%1,%2,%3}, [%4];" \
                 : "=r"(r0), "=r"(r1), "=r"(r2), "=r"(r3) : "r"(addr))

#define LDSM2T(r0, r1, addr) \
    asm volatile("ldmatrix.sync.aligned.m8n8.x2.trans.shared.b16 {%0,%1}, [%2];" \
                 : "=r"(r0), "=r"(r1) : "r"(addr))

#define CPA(dst, src, sz) \
    asm volatile("cp.async.ca.shared.global [%0], [%1], 16, %2;" \
                 :: "r"(dst), "l"(src), "r"(sz) : "memory")
#define CP_COMMIT() asm volatile("cp.async.commit_group;" ::: "memory")
#define CP_WAIT1()  asm volatile("cp.async.wait_group 1;" ::: "memory")
#define CP_WAIT0()  asm volatile("cp.async.wait_group 0;" ::: "memory")

// ============================ layout consts =================================
#define ROWB 80
#define MATB (128 * ROWB)             // 10240
#define ROW2 272
#define MATB2 (32 * ROW2)             // 8704
#define STG2 (2 * MATB)               // nn stage: A B          20480
#define SM22 (2 * STG2)               // 2-stage                40960
#define STGN (MATB + MATB2)           // nt stage: A B          18944
#define SMN  (2 * STGN)               // 37888

#define NCOL 256                      // Winograd GEMM N (4 n * 64 tiles)

// ======================== Winograd F(4,3) transforms ========================
// U = G g G^T: w [co][ci][3][3] -> U[conv][xi][co][ci] fp16 (xi = 6x6)
__global__ void wino_w(const float* __restrict__ w0, const float* __restrict__ w1,
                       const float* __restrict__ w2, const float* __restrict__ w3,
                       const float* __restrict__ w4, const float* __restrict__ w5,
                       fp16* __restrict__ U) {
    const float* ws[6] = {w0, w1, w2, w3, w4, w5};
    int conv = blockIdx.y;
    const float* w = ws[conv];
    int t = blockIdx.x * 256 + threadIdx.x;   // 262144 (co,ci) pairs
    int co = t >> 9, ci = t & 511;
    float g[3][3];
#pragma unroll
    for (int i = 0; i < 9; ++i) g[i / 3][i % 3] = w[(size_t)t * 9 + i];
    float a[6][3];
#pragma unroll
    for (int c = 0; c < 3; ++c) {
        a[0][c] = 0.25f * g[0][c];
        a[1][c] = (-1.f / 6.f) * (g[0][c] + g[1][c] + g[2][c]);
        a[2][c] = (-1.f / 6.f) * (g[0][c] - g[1][c] + g[2][c]);
        a[3][c] = (1.f / 24.f) * g[0][c] + (1.f / 12.f) * g[1][c] + (1.f / 6.f) * g[2][c];
        a[4][c] = (1.f / 24.f) * g[0][c] - (1.f / 12.f) * g[1][c] + (1.f / 6.f) * g[2][c];
        a[5][c] = g[2][c];
    }
    float u[6][6];
#pragma unroll
    for (int r = 0; r < 6; ++r) {
        u[r][0] = 0.25f * a[r][0];
        u[r][1] = (-1.f / 6.f) * (a[r][0] + a[r][1] + a[r][2]);
        u[r][2] = (-1.f / 6.f) * (a[r][0] - a[r][1] + a[r][2]);
        u[r][3] = (1.f / 24.f) * a[r][0] + (1.f / 12.f) * a[r][1] + (1.f / 6.f) * a[r][2];
        u[r][4] = (1.f / 24.f) * a[r][0] - (1.f / 12.f) * a[r][1] + (1.f / 6.f) * a[r][2];
        u[r][5] = a[r][2];
    }
#pragma unroll
    for (int xi = 0; xi < 36; ++xi)
        U[(((size_t)conv * 36 + xi) * 512 + co) * 512 + ci] =
            __float2half_rn(u[xi / 6][xi % 6]);
}

// V = B^T d B: x [n][c][32][32] fp32 -> V[inp][xi][ci][n*64+t] fp16
// tiles: 8x8 of 4x4 outputs; input patch 6x6 at (4ty-1, 4tx-1)
__global__ void wino_v(const float* __restrict__ xl, const float* __restrict__ xg,
                       fp16* __restrict__ V) {
    int z = blockIdx.y;                       // inp*4 + n
    int inp = z >> 2, n = z & 3;
    const float* x = (inp ? xg : xl) + (size_t)n * (CCH * HW);
    int idx = blockIdx.x * 256 + threadIdx.x; // 512*64 -> grid.x = 128
    int ci = idx >> 6, t = idx & 63;
    int ty = t >> 3, tx = t & 7;
    const float* xc = x + (size_t)ci * HW;
    int r0 = 4 * ty - 1, c0 = 4 * tx - 1;
    float d[6][6];
#pragma unroll
    for (int i = 0; i < 6; ++i)
#pragma unroll
        for (int j = 0; j < 6; ++j) {
            int rr = r0 + i, cc = c0 + j;
            d[i][j] = ((unsigned)rr < 32u && (unsigned)cc < 32u)
                          ? xc[rr * 32 + cc] : 0.f;
        }
    float e[6][6];
#pragma unroll
    for (int j = 0; j < 6; ++j) {
        e[0][j] =  4.f * d[0][j] - 5.f * d[2][j] + d[4][j];
        e[1][j] = -4.f * d[1][j] - 4.f * d[2][j] + d[3][j] + d[4][j];
        e[2][j] =  4.f * d[1][j] - 4.f * d[2][j] - d[3][j] + d[4][j];
        e[3][j] = -2.f * d[1][j] -       d[2][j] + 2.f * d[3][j] + d[4][j];
        e[4][j] =  2.f * d[1][j] -       d[2][j] - 2.f * d[3][j] + d[4][j];
        e[5][j] =  4.f * d[1][j] - 5.f * d[3][j] + d[5][j];
    }
    float v[6][6];
#pragma unroll
    for (int i = 0; i < 6; ++i) {
        v[i][0] =  4.f * e[i][0] - 5.f * e[i][2] + e[i][4];
        v[i][1] = -4.f * e[i][1] - 4.f * e[i][2] + e[i][3] + e[i][4];
        v[i][2] =  4.f * e[i][1] - 4.f * e[i][2] - e[i][3] + e[i][4];
        v[i][3] = -2.f * e[i][1] -       e[i][2] + 2.f * e[i][3] + e[i][4];
        v[i][4] =  2.f * e[i][1] -       e[i][2] - 2.f * e[i][3] + e[i][4];
        v[i][5] =  4.f * e[i][1] - 5.f * e[i][3] + e[i][5];
    }
#pragma unroll
    for (int xi = 0; xi < 36; ++xi)
        V[(((size_t)inp * 36 + xi) * 512 + ci) * NCOL + n * 64 + t] =
            __float2half_rn(v[xi / 6][xi % 6]);
}

// Wp fp32 -> fp16
__global__ void prep_wp(const float* __restrict__ wp1, const float* __restrict__ wp2,
                        fp16* __restrict__ wo) {
    int pidx = blockIdx.y;
    const float* w = pidx ? wp2 : wp1;
    int idx = blockIdx.x * 256 + threadIdx.x;
    wo[(size_t)pidx * 512 * 512 + idx] = __float2half_rn(w[idx]);
}

// ======================= mma inner phases (single A) ========================
__device__ __forceinline__ void mma_phase_nn(uint32_t st, uint32_t a_base,
                                             uint32_t b_base, float acc[4][4][4]) {
    uint32_t sA = st, sB = st + MATB;
#pragma unroll
    for (int kt = 0; kt < 2; ++kt) {
        uint32_t aa[4][4], bb[4][2];
#pragma unroll
        for (int mt = 0; mt < 4; ++mt) {
            uint32_t ad = a_base + (uint32_t)(mt * 16 * ROWB + kt * 32);
            LDSM4(aa[mt][0], aa[mt][1], aa[mt][2], aa[mt][3], sA + ad);
        }
#pragma unroll
        for (int p = 0; p < 2; ++p) {
            uint32_t bd = b_base + (uint32_t)(p * 16 * ROWB + kt * 32);
            uint32_t r0, r1, r2, r3;
            LDSM4(r0, r1, r2, r3, sB + bd);
            bb[2 * p][0] = r0; bb[2 * p][1] = r2;
            bb[2 * p + 1][0] = r1; bb[2 * p + 1][1] = r3;
        }
#pragma unroll
        for (int mt = 0; mt < 4; ++mt)
#pragma unroll
            for (int nt = 0; nt < 4; ++nt)
                mma_f16(acc[mt][nt], aa[mt], bb[nt]);
    }
}

__device__ __forceinline__ void mma_phase_nt(uint32_t st, uint32_t a_base,
                                             uint32_t bt_base, float acc[4][4][4]) {
    uint32_t sA = st, sB = st + MATB;
#pragma unroll
    for (int kt = 0; kt < 2; ++kt) {
        uint32_t aa[4][4], bb[4][2];
#pragma unroll
        for (int mt = 0; mt < 4; ++mt) {
            uint32_t ad = a_base + (uint32_t)(mt * 16 * ROWB + kt * 32);
            LDSM4(aa[mt][0], aa[mt][1], aa[mt][2], aa[mt][3], sA + ad);
        }
#pragma unroll
        for (int nt = 0; nt < 4; ++nt) {
            uint32_t bd = bt_base + (uint32_t)(kt * 16 * ROW2 + nt * 16);
            LDSM2T(bb[nt][0], bb[nt][1], sB + bd);
        }
#pragma unroll
        for (int mt = 0; mt < 4; ++mt)
#pragma unroll
            for (int nt = 0; nt < 4; ++nt)
                mma_f16(acc[mt][nt], aa[mt], bb[nt]);
    }
}

// ============ Winograd-domain GEMM: C[xi] = U[xi] x V[xi] ===================
// grid (2 tile-chunks, 4 co-chunks, 216 = conv*36+xi). Proven nt structure.
__global__ __launch_bounds__(256, 2)
void wino_gemm(const fp16* __restrict__ U, const fp16* __restrict__ V,
               fp16* __restrict__ C) {
    extern __shared__ unsigned char dsm[];
    const uint32_t sb = smem_u32(dsm);

    int tid = threadIdx.x, wid = tid >> 5, lid = tid & 31;
    int warp_m = wid >> 2, warp_n = wid & 3;
    int z = blockIdx.z;
    int conv = z / 36, xi = z % 36;
    int inp = (conv < 3) ? 0 : 1;
    int tile0 = blockIdx.x * 128, co0 = blockIdx.y * 128;
    const fp16* A = U + ((size_t)conv * 36 + xi) * 512 * 512;
    const fp16* B = V + ((size_t)inp * 36 + xi) * 512 * NCOL;
    fp16* Cb = C + ((size_t)conv * 36 + xi) * 512 * NCOL;

    float acc[4][4][4];
#pragma unroll
    for (int mt = 0; mt < 4; ++mt)
#pragma unroll
        for (int nt = 0; nt < 4; ++nt)
#pragma unroll
            for (int kk = 0; kk < 4; ++kk) acc[mt][nt][kk] = 0.f;

    int grp = lid >> 3, lr = lid & 7;
    uint32_t a_base = (uint32_t)((warp_m * 64 + (grp & 1) * 8 + lr) * ROWB + (grp >> 1) * 16);
    int l16 = lid & 15;
    uint32_t bt_base = (uint32_t)(l16 * ROW2 + warp_n * 64);

    int row = tid >> 1, half = tid & 1;
    uint32_t dstA = (uint32_t)(row * ROWB + half * 32);
    int cir = tid >> 3, seg = tid & 7;
    uint32_t dstB = (uint32_t)(cir * ROW2 + seg * 32);

    auto prefetch = [&](int ch, int st) {
        uint32_t s0b = sb + st * STGN;
        int ci0 = ch << 5;
        size_t wof = (size_t)(co0 + row) * 512 + ci0 + half * 16;
        uint32_t da = s0b + dstA;
        CPA(da,      A + wof,     16u);
        CPA(da + 16, A + wof + 8, 16u);
        size_t bof = (size_t)(ci0 + cir) * NCOL + tile0 + seg * 16;
        uint32_t db = s0b + MATB + dstB;
        CPA(db,      B + bof,     16u);
        CPA(db + 16, B + bof + 8, 16u);
    };

    prefetch(0, 0); CP_COMMIT();
    for (int ch = 0; ch < 16; ++ch) {
        if (ch + 1 < 16) { prefetch(ch + 1, (ch + 1) & 1); CP_COMMIT(); CP_WAIT1(); }
        else CP_WAIT0();
        __syncthreads();
        mma_phase_nt(sb + (ch & 1) * STGN, a_base, bt_base, acc);
        __syncthreads();
    }

#pragma unroll
    for (int mt = 0; mt < 4; ++mt) {
        int m = co0 + warp_m * 64 + mt * 16 + (lid >> 2);
#pragma unroll
        for (int nt = 0; nt < 4; ++nt) {
            int sc = tile0 + warp_n * 32 + nt * 8 + (lid & 3) * 2;
            __half2 p0 = __floats2half2_rn(acc[mt][nt][0], acc[mt][nt][1]);
            __half2 p1 = __floats2half2_rn(acc[mt][nt][2], acc[mt][nt][3]);
            *(uint32_t*)&Cb[(size_t)m * NCOL + sc] = *(uint32_t*)&p0;
            *(uint32_t*)&Cb[(size_t)(m + 8) * NCOL + sc] = *(uint32_t*)&p1;
        }
    }
}

// ================ inverse transform: Y = A^T M A -> qkv =====================
// grid (128, 4 n, 6 conv); thread = (co, tile); tile = 8x8 grid of 4x4 outputs
__global__ void wino_inv(const fp16* __restrict__ C, fp16* __restrict__ q1) {
    int conv = blockIdx.z, n = blockIdx.y;
    int idx = blockIdx.x * 256 + threadIdx.x;   // 512co * 64t
    int co = idx >> 6, t = idx & 63;
    int ty = t >> 3, tx = t & 7;
    const size_t XSTR = (size_t)512 * NCOL;
    size_t base = (size_t)conv * 36 * XSTR + (size_t)co * NCOL + n * 64 + t;
    float m[6][6];
#pragma unroll
    for (int xi = 0; xi < 36; ++xi)
        m[xi / 6][xi % 6] = __half2float(C[base + (size_t)xi * XSTR]);
    float p[4][6];
#pragma unroll
    for (int j = 0; j < 6; ++j) {
        p[0][j] = m[0][j] + m[1][j] + m[2][j] + m[3][j] + m[4][j];
        p[1][j] = m[1][j] - m[2][j] + 2.f * m[3][j] - 2.f * m[4][j];
        p[2][j] = m[1][j] + m[2][j] + 4.f * m[3][j] + 4.f * m[4][j];
        p[3][j] = m[1][j] - m[2][j] + 8.f * m[3][j] - 8.f * m[4][j] + m[5][j];
    }
    float y[4][4];
#pragma unroll
    for (int i = 0; i < 4; ++i) {
        y[i][0] = p[i][0] + p[i][1] + p[i][2] + p[i][3] + p[i][4];
        y[i][1] = p[i][1] - p[i][2] + 2.f * p[i][3] - 2.f * p[i][4];
        y[i][2] = p[i][1] + p[i][2] + 4.f * p[i][3] + 4.f * p[i][4];
        y[i][3] = p[i][1] - p[i][2] + 8.f * p[i][3] - 8.f * p[i][4] + p[i][5];
    }
    fp16* o = q1 + ((size_t)conv * NB + n) * (CCH * HW) + (size_t)co * HW;
    int oy = 4 * ty, ox = 4 * tx;
#pragma unroll
    for (int i = 0; i < 4; ++i) {
        __half2 r0 = __floats2half2_rn(y[i][0], y[i][1]);
        __half2 r1 = __floats2half2_rn(y[i][2], y[i][3]);
        *(uint32_t*)&o[(oy + i) * 32 + ox] = *(uint32_t*)&r0;
        *(uint32_t*)&o[(oy + i) * 32 + ox + 2] = *(uint32_t*)&r1;
    }
}

// ================== QK^T: single fp16, 2-stage cp.async =====================
// grid (4 ck, 4 cq, 64): z<32 -> (q_g,k_l)->att0 ; z>=32 -> (q_l,k_g)->att1
__global__ __launch_bounds__(256, 2)
void qk_mma_kernel(const fp16* __restrict__ qk1, float* __restrict__ att) {
    extern __shared__ unsigned char dsm[];
    const uint32_t sb = smem_u32(dsm);
    const size_t QKV_N = (size_t)NB * CCH * HW;
    const size_t ATT_N = (size_t)NB * NHD * 512 * 512;

    int tid = threadIdx.x, wid = tid >> 5, lid = tid & 31;
    int warp_m = wid >> 2, warp_n = wid & 3;
    int z = blockIdx.z, sel = z >> 5, nh = z & 31;
    int n = nh >> 3, h = nh & 7;
    int ck0 = blockIdx.x * 128, cq0 = blockIdx.y * 128;
    size_t base = (size_t)n * (CCH * HW) + h * DHEAD;
    const fp16* qb = qk1 + (sel ? 1 : 4) * QKV_N + base;
    const fp16* kb = qk1 + (sel ? 3 : 0) * QKV_N + base;

    float acc[4][4][4];
#pragma unroll
    for (int mt = 0; mt < 4; ++mt)
#pragma unroll
        for (int nt = 0; nt < 4; ++nt)
#pragma unroll
            for (int kk = 0; kk < 4; ++kk) acc[mt][nt][kk] = 0.f;

    int grp = lid >> 3, lr = lid & 7;
    uint32_t a_base = (uint32_t)((warp_m * 64 + (grp & 1) * 8 + lr) * ROWB + (grp >> 1) * 16);
    uint32_t b_base = (uint32_t)((warp_n * 32 + (grp & 1) * 8 + lr) * ROWB + (grp >> 1) * 16);

    int row = tid >> 1, half = tid & 1;
    uint32_t dstA = (uint32_t)(row * ROWB + half * 32);

    auto prefetch = [&](int ch, int st) {
        uint32_t s0b = sb + st * STG2;
        int ci0 = ch << 5;
        size_t qof = (size_t)(cq0 + row) * HW + ci0 + half * 16;
        size_t kof = (size_t)(ck0 + row) * HW + ci0 + half * 16;
        uint32_t da = s0b + dstA;
        CPA(da,      qb + qof,     16u);
        CPA(da + 16, qb + qof + 8, 16u);
        uint32_t db = s0b + MATB + dstA;
        CPA(db,      kb + kof,     16u);
        CPA(db + 16, kb + kof + 8, 16u);
    };

    prefetch(0, 0); CP_COMMIT();
    for (int ch = 0; ch < 4; ++ch) {
        if (ch + 1 < 4) { prefetch(ch + 1, (ch + 1) & 1); CP_COMMIT(); CP_WAIT1(); }
        else CP_WAIT0();
        __syncthreads();
        mma_phase_nn(sb + (ch & 1) * STG2, a_base, b_base, acc);
        __syncthreads();
    }

    const float SC = 0.08838834764831845f;   // 1/sqrt(128)
    float* ab = att + sel * ATT_N + (size_t)(n * NHD + h) * 512 * 512;
#pragma unroll
    for (int mt = 0; mt < 4; ++mt) {
        int m = cq0 + warp_m * 64 + mt * 16 + (lid >> 2);
#pragma unroll
        for (int nt = 0; nt < 4; ++nt) {
            int sc = ck0 + warp_n * 32 + nt * 8 + (lid & 3) * 2;
            *(float2*)(ab + (size_t)m * 512 + sc) =
                make_float2(acc[mt][nt][0] * SC, acc[mt][nt][1] * SC);
            *(float2*)(ab + (size_t)(m + 8) * 512 + sc) =
                make_float2(acc[mt][nt][2] * SC, acc[mt][nt][3] * SC);
        }
    }
}

// ----------------- softmax: fp32 in -> fp16 out ------------------------------
__global__ void softmax_kernel(const float* __restrict__ att, fp16* __restrict__ a1) {
    int row  = blockIdx.x * 8 + (threadIdx.x >> 5);
    int lane = threadIdx.x & 31;
    const float* p = att + (size_t)row * 512;
    fp16* po = a1 + (size_t)row * 512;
    float v[16];
    float m = -1e30f;
#pragma unroll
    for (int i = 0; i < 16; ++i) { v[i] = p[lane + i * 32]; m = fmaxf(m, v[i]); }
#pragma unroll
    for (int o = 16; o; o >>= 1) m = fmaxf(m, __shfl_xor_sync(0xffffffffu, m, o));
    float s = 0.f;
#pragma unroll
    for (int i = 0; i < 16; ++i) { v[i] = __expf(v[i] - m); s += v[i]; }
#pragma unroll
    for (int o = 16; o; o >>= 1) s += __shfl_xor_sync(0xffffffffu, s, o);
    float inv = 1.f / s;
#pragma unroll
    for (int i = 0; i < 16; ++i)
        po[lane + i * 32] = __float2half_rn(v[i] * inv);
}

// ================== AV: single fp16, 2-stage (B trans) ======================
// grid (4 cq, 64): y<32 -> att0 @ v_l -> y_g ; y>=32 -> att1 @ v_g -> y_l
__global__ __launch_bounds__(256, 2)
void av_mma_kernel(const fp16* __restrict__ a1, const fp16* __restrict__ qk1,
                   fp16* __restrict__ y1) {
    extern __shared__ unsigned char dsm[];
    const uint32_t sb = smem_u32(dsm);
    const size_t QKV_N = (size_t)NB * CCH * HW;
    const size_t ATT_N = (size_t)NB * NHD * 512 * 512;

    int tid = threadIdx.x, wid = tid >> 5, lid = tid & 31;
    int warp_m = wid >> 2, warp_n = wid & 3;
    int z = blockIdx.y, sel = z >> 5, nh = z & 31;
    int n = nh >> 3, h = nh & 7;
    int cq0 = blockIdx.x * 128;
    const fp16* ab = a1 + sel * ATT_N + (size_t)(n * NHD + h) * 512 * 512;
    size_t vbo = (size_t)n * (CCH * HW) + h * DHEAD;
    const fp16* vb = qk1 + (sel ? 5 : 2) * QKV_N + vbo;

    float acc[4][4][4];
#pragma unroll
    for (int mt = 0; mt < 4; ++mt)
#pragma unroll
        for (int nt = 0; nt < 4; ++nt)
#pragma unroll
            for (int kk = 0; kk < 4; ++kk) acc[mt][nt][kk] = 0.f;

    int grp = lid >> 3, lr = lid & 7;
    uint32_t a_base = (uint32_t)((warp_m * 64 + (grp & 1) * 8 + lr) * ROWB + (grp >> 1) * 16);
    int l16 = lid & 15;
    uint32_t bt_base = (uint32_t)(l16 * ROW2 + warp_n * 64);

    int row = tid >> 1, half = tid & 1;
    uint32_t dstA = (uint32_t)(row * ROWB + half * 32);
    int ckr = tid >> 3, seg = tid & 7;
    uint32_t dstB = (uint32_t)(ckr * ROW2 + seg * 32);

    auto prefetch = [&](int ch, int st) {
        uint32_t s0b = sb + st * STGN;
        int ci0 = ch << 5;
        size_t aof = (size_t)(cq0 + row) * 512 + ci0 + half * 16;
        uint32_t da = s0b + dstA;
        CPA(da,      ab + aof,     16u);
        CPA(da + 16, ab + aof + 8, 16u);
        size_t vof = (size_t)(ci0 + ckr) * HW + seg * 16;
        uint32_t db = s0b + MATB + dstB;
        CPA(db,      vb + vof,     16u);
        CPA(db + 16, vb + vof + 8, 16u);
    };

    prefetch(0, 0); CP_COMMIT();
    for (int ch = 0; ch < 16; ++ch) {
        if (ch + 1 < 16) { prefetch(ch + 1, (ch + 1) & 1); CP_COMMIT(); CP_WAIT1(); }
        else CP_WAIT0();
        __syncthreads();
        mma_phase_nt(sb + (ch & 1) * STGN, a_base, bt_base, acc);
        __syncthreads();
    }

    fp16* yb = y1 + (sel ? QKV_N : 0) + vbo;
#pragma unroll
    for (int mt = 0; mt < 4; ++mt) {
        int m = cq0 + warp_m * 64 + mt * 16 + (lid >> 2);
#pragma unroll
        for (int nt = 0; nt < 4; ++nt) {
            int dc = warp_n * 32 + nt * 8 + (lid & 3) * 2;
            __half2 p0 = __floats2half2_rn(acc[mt][nt][0], acc[mt][nt][1]);
            __half2 p1 = __floats2half2_rn(acc[mt][nt][2], acc[mt][nt][3]);
            *(uint32_t*)&yb[(size_t)m * HW + dc] = *(uint32_t*)&p0;
            *(uint32_t*)&yb[(size_t)(m + 8) * HW + dc] = *(uint32_t*)&p1;
        }
    }
}

// ========= 1x1 proj + residual: single fp16, 2-stage (B trans) ==============
// grid (8 s, 4 co, 8): z<4 -> Wp1 @ y_l + x_l -> out_l ; else Wp2 @ y_g + x_g
__global__ __launch_bounds__(256, 2)
void proj_mma_kernel(const fp16* __restrict__ y1, const fp16* __restrict__ wp1,
                     const float* __restrict__ x_l, const float* __restrict__ x_g,
                     const float* __restrict__ rwp, float* __restrict__ out) {
    extern __shared__ unsigned char dsm[];
    const uint32_t sb = smem_u32(dsm);
    const size_t QKV_N = (size_t)NB * CCH * HW;

    int tid = threadIdx.x, wid = tid >> 5, lid = tid & 31;
    int warp_m = wid >> 2, warp_n = wid & 3;
    int z = blockIdx.z, sel = z >> 2, n = z & 3;    // sel 0: out_l, 1: out_g
    int sp0 = blockIdx.x * 128, co0 = blockIdx.y * 128;
    const fp16* yb = y1 + (sel ? 0 : QKV_N) + (size_t)n * (CCH * HW);
    const fp16* wb = wp1 + (size_t)sel * 512 * 512;
    const float* xres = sel ? x_g : x_l;
    float* outb = out + (size_t)sel * QKV_N;

    float acc[4][4][4];
#pragma unroll
    for (int mt = 0; mt < 4; ++mt)
#pragma unroll
        for (int nt = 0; nt < 4; ++nt)
#pragma unroll
            for (int kk = 0; kk < 4; ++kk) acc[mt][nt][kk] = 0.f;

    int grp = lid >> 3, lr = lid & 7;
    uint32_t a_base = (uint32_t)((warp_m * 64 + (grp & 1) * 8 + lr) * ROWB + (grp >> 1) * 16);
    int l16 = lid & 15;
    uint32_t bt_base = (uint32_t)(l16 * ROW2 + warp_n * 64);

    int row = tid >> 1, half = tid & 1;
    uint32_t dstA = (uint32_t)(row * ROWB + half * 32);
    int cir = tid >> 3, seg = tid & 7;
    uint32_t dstB = (uint32_t)(cir * ROW2 + seg * 32);

    auto prefetch = [&](int ch, int st) {
        uint32_t s0b = sb + st * STGN;
        int ci0 = ch << 5;
        size_t wof = (size_t)(co0 + row) * 512 + ci0 + half * 16;
        uint32_t da = s0b + dstA;
        CPA(da,      wb + wof,     16u);
        CPA(da + 16, wb + wof + 8, 16u);
        size_t yof = (size_t)(ci0 + cir) * HW + sp0 + seg * 16;
        uint32_t db = s0b + MATB + dstB;
        CPA(db,      yb + yof,     16u);
        CPA(db + 16, yb + yof + 8, 16u);
    };

    prefetch(0, 0); CP_COMMIT();
    for (int ch = 0; ch < 16; ++ch) {
        if (ch + 1 < 16) { prefetch(ch + 1, (ch + 1) & 1); CP_COMMIT(); CP_WAIT1(); }
        else CP_WAIT0();
        __syncthreads();
        mma_phase_nt(sb + (ch & 1) * STGN, a_base, bt_base, acc);
        __syncthreads();
    }

    float rw = *rwp;
#pragma unroll
    for (int mt = 0; mt < 4; ++mt) {
        int m = co0 + warp_m * 64 + mt * 16 + (lid >> 2);
#pragma unroll
        for (int nt = 0; nt < 4; ++nt) {
            int sc = sp0 + warp_n * 32 + nt * 8 + (lid & 3) * 2;
            size_t b0 = ((size_t)n * CCH + m) * HW + sc;
            size_t b1 = ((size_t)n * CCH + m + 8) * HW + sc;
            float2 x0 = *(const float2*)(xres + b0);
            float2 x1 = *(const float2*)(xres + b1);
            *(float2*)(outb + b0) = make_float2(x0.x + rw * acc[mt][nt][0],
                                                x0.y + rw * acc[mt][nt][1]);
            *(float2*)(outb + b1) = make_float2(x1.x + rw * acc[mt][nt][2],
                                                x1.y + rw * acc[mt][nt][3]);
        }
    }
}

// ------------------------------- launcher -----------------------------------
extern "C" void kernel_launch(void* const* d_in, const int* in_sizes, int n_in,
                              void* d_out, int out_size) {
    (void)in_sizes; (void)n_in; (void)out_size;
    const float* x_l = (const float*)d_in[0];
    const float* x_g = (const float*)d_in[1];
    const float* Wp1 = (const float*)d_in[8];
    const float* Wp2 = (const float*)d_in[9];
    const float* rw  = (const float*)d_in[10];
    float* out = (float*)d_out;

    void* p;
    cudaGetSymbolAddress(&p, g_U);   fp16* U   = (fp16*)p;
    cudaGetSymbolAddress(&p, g_V);   fp16* V   = (fp16*)p;
    cudaGetSymbolAddress(&p, g_C);   fp16* C   = (fp16*)p;
    cudaGetSymbolAddress(&p, g_q1);  fp16* q1  = (fp16*)p;
    cudaGetSymbolAddress(&p, g_att); float* attp = (float*)p;
    cudaGetSymbolAddress(&p, g_a1);  fp16* a1  = (fp16*)p;
    cudaGetSymbolAddress(&p, g_y1);  fp16* y1  = (fp16*)p;
    cudaGetSymbolAddress(&p, g_wp1); fp16* wp1 = (fp16*)p;

    cudaFuncSetAttribute(wino_gemm,       cudaFuncAttributeMaxDynamicSharedMemorySize, SMN);
    cudaFuncSetAttribute(qk_mma_kernel,   cudaFuncAttributeMaxDynamicSharedMemorySize, SM22);
    cudaFuncSetAttribute(av_mma_kernel,   cudaFuncAttributeMaxDynamicSharedMemorySize, SMN);
    cudaFuncSetAttribute(proj_mma_kernel, cudaFuncAttributeMaxDynamicSharedMemorySize, SMN);

    wino_w<<<dim3(1024, 6), 256>>>(
        (const float*)d_in[2], (const float*)d_in[3], (const float*)d_in[4],
        (const float*)d_in[5], (const float*)d_in[6], (const float*)d_in[7], U);
    wino_v<<<dim3(128, 8), 256>>>(x_l, x_g, V);
    prep_wp<<<dim3(1024, 2), 256>>>(Wp1, Wp2, wp1);

    wino_gemm<<<dim3(2, 4, 216), 256, SMN>>>(U, V, C);
    wino_inv<<<dim3(128, 4, 6), 256>>>(C, q1);

    qk_mma_kernel<<<dim3(4, 4, 64), 256, SM22>>>(q1, attp);

    softmax_kernel<<<4096, 256>>>(attp, a1);

    av_mma_kernel<<<dim3(4, 64), 256, SMN>>>(a1, q1, y1);

    proj_mma_kernel<<<dim3(8, 4, 8), 256, SMN>>>(y1, wp1, x_l, x_g, rw, out);
}